// round 8
// baseline (speedup 1.0000x reference)
#include <cuda_runtime.h>
#include <cuda_fp16.h>
#include <cstdint>

// ---------------------------------------------------------------------------
// CategoricalGINEncoder on GB300 (sm_103a) — round 8
//  round 7 (fp16 datapath) + PERSISTENT GEMM kernels:
//   each of 3 GEMMs is a persistent kernel (1 CTA/SM) that loads its 256x256
//   weight matrix into smem ONCE (fp32->half at STS), then loops over 64-row
//   tiles with a barrier-free LDSM+MMA inner loop.
//   kG1: h = LN1(relu(relu(a1+b1a)@W1b + b1b))
//   kG2: u = h@W2a
//   kG3: out = LN2(relu(a2+b2a)@W2b + b2b)
// ---------------------------------------------------------------------------

#define NMAX 100000
#define EMAX 1600000
#define DIM  256

__device__ __half g_h0[(size_t)NMAX * DIM];
__device__ __half g_h1[(size_t)NMAX * DIM];
__device__ __half g_tabh[(size_t)4 * 1024 * DIM];
__device__ int    g_deg[NMAX];
__device__ int    g_rowptr[NMAX + 1];
__device__ int    g_cursor[NMAX];
__device__ int    g_csr[EMAX];

// ------------------------------- CSR build --------------------------------

__global__ void k_count4(const int* __restrict__ ei, int* __restrict__ deg,
                         int E) {
    int i = (blockIdx.x * blockDim.x + threadIdx.x) * 4;
    if (i >= E) return;
    if (i + 3 < E) {
        int4 d = *(const int4*)(ei + E + i);
        atomicAdd(&deg[d.x], 1);
        atomicAdd(&deg[d.y], 1);
        atomicAdd(&deg[d.z], 1);
        atomicAdd(&deg[d.w], 1);
    } else {
        for (; i < E; ++i) atomicAdd(&deg[ei[E + i]], 1);
    }
}

__global__ void k_scan(const int* __restrict__ deg, int* __restrict__ rowptr,
                       int* __restrict__ cursor, int n) {
    __shared__ int sh[1024];
    int t = threadIdx.x;
    int chunk = (n + 1023) >> 10;
    int lo = t * chunk;
    int hi = min(lo + chunk, n);
    int s = 0;
    for (int i = lo; i < hi; ++i) s += deg[i];
    sh[t] = s;
    __syncthreads();
    for (int off = 1; off < 1024; off <<= 1) {
        int v = (t >= off) ? sh[t - off] : 0;
        __syncthreads();
        sh[t] += v;
        __syncthreads();
    }
    int run = (t == 0) ? 0 : sh[t - 1];
    for (int i = lo; i < hi; ++i) {
        rowptr[i] = run;
        cursor[i] = run;
        run += deg[i];
    }
    if (lo < n && hi == n) rowptr[n] = run;
}

__global__ void k_fill4(const int* __restrict__ ei, int* __restrict__ cursor,
                        int* __restrict__ csr, int E) {
    int i = (blockIdx.x * blockDim.x + threadIdx.x) * 4;
    if (i >= E) return;
    if (i + 3 < E) {
        int4 s = *(const int4*)(ei + i);
        int4 d = *(const int4*)(ei + E + i);
        csr[atomicAdd(&cursor[d.x], 1)] = s.x;
        csr[atomicAdd(&cursor[d.y], 1)] = s.y;
        csr[atomicAdd(&cursor[d.z], 1)] = s.z;
        csr[atomicAdd(&cursor[d.w], 1)] = s.w;
    } else {
        for (; i < E; ++i)
            csr[atomicAdd(&cursor[ei[E + i]], 1)] = ei[i];
    }
}

// ------------------------ embedding tables + z0 -----------------------------

__global__ void k_tab(const float* __restrict__ e0, const float* __restrict__ e1,
                      const float* __restrict__ e2, const float* __restrict__ e3,
                      const float* __restrict__ w1a, __half* __restrict__ T,
                      int V) {
    int f = blockIdx.y;
    const float* emb = (f == 0) ? e0 : (f == 1) ? e1 : (f == 2) ? e2 : e3;
    int v0 = blockIdx.x * 16;
    __shared__ float es[16 * 64];
    int tid = threadIdx.x;
    #pragma unroll
    for (int i = 0; i < 4; ++i) {
        int idx = i * 256 + tid;
        int v = idx >> 6, k = idx & 63;
        es[idx] = (v0 + v < V) ? emb[(v0 + v) * 64 + k] : 0.f;
    }
    __syncthreads();
    float acc[16];
    #pragma unroll
    for (int v = 0; v < 16; ++v) acc[v] = 0.f;
    int c = tid;
    #pragma unroll 4
    for (int k = 0; k < 64; ++k) {
        float w = w1a[(f * 64 + k) * 256 + c];
        #pragma unroll
        for (int v = 0; v < 16; ++v) acc[v] = fmaf(es[v * 64 + k], w, acc[v]);
    }
    #pragma unroll
    for (int v = 0; v < 16; ++v)
        if (v0 + v < V)
            T[((size_t)f * 1024 + v0 + v) * 256 + c] = __float2half_rn(acc[v]);
}

__device__ __forceinline__ void addh8(float* a, uint4 v) {
    float2 f;
    f = __half22float2(*(__half2*)&v.x); a[0] += f.x; a[1] += f.y;
    f = __half22float2(*(__half2*)&v.y); a[2] += f.x; a[3] += f.y;
    f = __half22float2(*(__half2*)&v.z); a[4] += f.x; a[5] += f.y;
    f = __half22float2(*(__half2*)&v.w); a[6] += f.x; a[7] += f.y;
}

__global__ void k_z0(const int* __restrict__ xc, const __half* __restrict__ T,
                     __half* __restrict__ Z, int M) {
    int idx = blockIdx.x * blockDim.x + threadIdx.x;
    if (idx >= M * 32) return;
    int node = idx >> 5;
    int q = idx & 31;
    int c0 = xc[node * 4 + 0];
    int c1 = xc[node * 4 + 1];
    int c2 = xc[node * 4 + 2];
    int c3 = xc[node * 4 + 3];
    float a[8] = {0.f, 0.f, 0.f, 0.f, 0.f, 0.f, 0.f, 0.f};
    addh8(a, *(const uint4*)(T + ((size_t)0 * 1024 + c0) * 256 + q * 8));
    addh8(a, *(const uint4*)(T + ((size_t)1 * 1024 + c1) * 256 + q * 8));
    addh8(a, *(const uint4*)(T + ((size_t)2 * 1024 + c2) * 256 + q * 8));
    addh8(a, *(const uint4*)(T + ((size_t)3 * 1024 + c3) * 256 + q * 8));
    __half2 h0 = __floats2half2_rn(a[0], a[1]);
    __half2 h1 = __floats2half2_rn(a[2], a[3]);
    __half2 h2 = __floats2half2_rn(a[4], a[5]);
    __half2 h3 = __floats2half2_rn(a[6], a[7]);
    uint4 o;
    o.x = *(uint32_t*)&h0; o.y = *(uint32_t*)&h1;
    o.z = *(uint32_t*)&h2; o.w = *(uint32_t*)&h3;
    ((uint4*)(Z + (size_t)node * 256))[q] = o;
}

// --------------------------- aggregation (half) ----------------------------

__global__ void k_agg(const __half* __restrict__ X, __half* __restrict__ Y,
                      const int* __restrict__ rowptr, const int* __restrict__ csr,
                      int M) {
    int w = (blockIdx.x * blockDim.x + threadIdx.x) >> 5;
    int lane = threadIdx.x & 31;
    if (w >= M) return;
    float a[8] = {0.f, 0.f, 0.f, 0.f, 0.f, 0.f, 0.f, 0.f};
    addh8(a, ((const uint4*)(X + (size_t)w * DIM))[lane]);
    int e = rowptr[w], end = rowptr[w + 1];
    for (; e + 1 < end; e += 2) {
        int s0 = csr[e];
        int s1 = csr[e + 1];
        uint4 u = ((const uint4*)(X + (size_t)s0 * DIM))[lane];
        uint4 v = ((const uint4*)(X + (size_t)s1 * DIM))[lane];
        addh8(a, u);
        addh8(a, v);
    }
    if (e < end) {
        int s = csr[e];
        addh8(a, ((const uint4*)(X + (size_t)s * DIM))[lane]);
    }
    __half2 h0 = __floats2half2_rn(a[0], a[1]);
    __half2 h1 = __floats2half2_rn(a[2], a[3]);
    __half2 h2 = __floats2half2_rn(a[4], a[5]);
    __half2 h3 = __floats2half2_rn(a[6], a[7]);
    uint4 o;
    o.x = *(uint32_t*)&h0; o.y = *(uint32_t*)&h1;
    o.z = *(uint32_t*)&h2; o.w = *(uint32_t*)&h3;
    ((uint4*)(Y + (size_t)w * DIM))[lane] = o;
}

// ------------------------ persistent GEMM kernel ----------------------------
// W (256x256) resident in smem for the CTA's lifetime; loop over 64-row tiles.
// 8 warps (2M x 4N), warp tile 32x64, m16n8k16 f16 MMA, fp32 accum.

#define WPH  264
#define W_SZ (256 * WPH)            // 67584 halves = 135168 B
#define XPH  264
#define XS_H (64 * XPH)             // 16896 halves = 33792 B
#define PG_SMEM_BYTES ((W_SZ + XS_H) * 2 + 64 * 4 * 8)   // 171008 B

__device__ __forceinline__ void ldsm4(uint32_t* r, uint32_t addr) {
    asm volatile("ldmatrix.sync.aligned.m8n8.x4.shared.b16 {%0,%1,%2,%3},[%4];"
                 : "=r"(r[0]), "=r"(r[1]), "=r"(r[2]), "=r"(r[3]) : "r"(addr));
}
__device__ __forceinline__ void ldsm4t(uint32_t* r, uint32_t addr) {
    asm volatile("ldmatrix.sync.aligned.m8n8.x4.trans.shared.b16 {%0,%1,%2,%3},[%4];"
                 : "=r"(r[0]), "=r"(r[1]), "=r"(r[2]), "=r"(r[3]) : "r"(addr));
}
__device__ __forceinline__ void mma16(float* c, const uint32_t* a,
                                      uint32_t b0, uint32_t b1) {
    asm volatile(
        "mma.sync.aligned.m16n8k16.row.col.f32.f16.f16.f32 "
        "{%0,%1,%2,%3},{%4,%5,%6,%7},{%8,%9},{%0,%1,%2,%3};\n"
        : "+f"(c[0]), "+f"(c[1]), "+f"(c[2]), "+f"(c[3])
        : "r"(a[0]), "r"(a[1]), "r"(a[2]), "r"(a[3]), "r"(b0), "r"(b1));
}

__global__ void __launch_bounds__(256, 1) k_pgemm(
    const __half* __restrict__ In, const float* __restrict__ bIn,
    const float* __restrict__ Wf,  const float* __restrict__ b2,
    const float* __restrict__ lng, const float* __restrict__ lnb,
    __half* __restrict__ OutH, float* __restrict__ OutF,
    int M, int nTiles, int reluLN, int doLN) {
    extern __shared__ __half smh[];
    __half* WS = smh;
    __half* XS = smh + W_SZ;
    float2* part = (float2*)(smh + W_SZ + XS_H);   // [64][4]

    const int tid  = threadIdx.x;
    const int warp = tid >> 5, lane = tid & 31;
    const int wm = warp >> 2;
    const int wn = warp & 3;
    const int g  = lane >> 2;
    const int tq = lane & 3;
    const int aro = ((lane >> 3) & 1) * 8 + (lane & 7);
    const int kco = (lane >> 4) * 8;
    uint32_t xs_b = (uint32_t)__cvta_generic_to_shared(XS);
    uint32_t ws_b = (uint32_t)__cvta_generic_to_shared(WS);

    // ---- load + convert W into smem (once per CTA) ----
    {
        const int krow = tid >> 5;       // 0..7
        const int n8 = tid & 31;         // 8-col group
        #pragma unroll 8
        for (int i = 0; i < 32; ++i) {
            int row = krow + i * 8;
            float4 a4 = *(const float4*)(Wf + (size_t)row * 256 + n8 * 8);
            float4 b4 = *(const float4*)(Wf + (size_t)row * 256 + n8 * 8 + 4);
            __half2 p0 = __floats2half2_rn(a4.x, a4.y);
            __half2 p1 = __floats2half2_rn(a4.z, a4.w);
            __half2 p2 = __floats2half2_rn(b4.x, b4.y);
            __half2 p3 = __floats2half2_rn(b4.z, b4.w);
            uint4 o;
            o.x = *(uint32_t*)&p0; o.y = *(uint32_t*)&p1;
            o.z = *(uint32_t*)&p2; o.w = *(uint32_t*)&p3;
            *(uint4*)(WS + row * WPH + n8 * 8) = o;
        }
    }

    for (int t = blockIdx.x; t < nTiles; t += gridDim.x) {
        const long blockRow = (long)t * 64;

        // ---- stage XS = half( [relu](In + bIn) ) ----
        #pragma unroll
        for (int i = 0; i < 8; ++i) {
            int id = i * 256 + tid;
            int row = id >> 5;
            int q = id & 31;
            long r = blockRow + row;
            if (r > M - 1) r = M - 1;
            uint4 v = ((const uint4*)(In + r * 256))[q];
            if (bIn) {
                float4 ba = *(const float4*)(bIn + q * 8);
                float4 bb = *(const float4*)(bIn + q * 8 + 4);
                float f[8];
                float2 tt;
                tt = __half22float2(*(__half2*)&v.x); f[0] = tt.x; f[1] = tt.y;
                tt = __half22float2(*(__half2*)&v.y); f[2] = tt.x; f[3] = tt.y;
                tt = __half22float2(*(__half2*)&v.z); f[4] = tt.x; f[5] = tt.y;
                tt = __half22float2(*(__half2*)&v.w); f[6] = tt.x; f[7] = tt.y;
                f[0] = fmaxf(f[0] + ba.x, 0.f); f[1] = fmaxf(f[1] + ba.y, 0.f);
                f[2] = fmaxf(f[2] + ba.z, 0.f); f[3] = fmaxf(f[3] + ba.w, 0.f);
                f[4] = fmaxf(f[4] + bb.x, 0.f); f[5] = fmaxf(f[5] + bb.y, 0.f);
                f[6] = fmaxf(f[6] + bb.z, 0.f); f[7] = fmaxf(f[7] + bb.w, 0.f);
                __half2 h0 = __floats2half2_rn(f[0], f[1]);
                __half2 h1 = __floats2half2_rn(f[2], f[3]);
                __half2 h2 = __floats2half2_rn(f[4], f[5]);
                __half2 h3 = __floats2half2_rn(f[6], f[7]);
                v.x = *(uint32_t*)&h0; v.y = *(uint32_t*)&h1;
                v.z = *(uint32_t*)&h2; v.w = *(uint32_t*)&h3;
            }
            *(uint4*)(XS + row * XPH + q * 8) = v;
        }
        __syncthreads();   // XS ready (and W, for the first tile)

        // ---- GEMM: barrier-free inner loop, all operands in smem ----
        float c[2][8][4];
        #pragma unroll
        for (int i = 0; i < 2; ++i)
            #pragma unroll
            for (int j = 0; j < 8; ++j)
                #pragma unroll
                for (int k = 0; k < 4; ++k) c[i][j][k] = 0.f;

        #pragma unroll 4
        for (int kt = 0; kt < 16; ++kt) {
            const int kb = kt * 16;
            uint32_t a[2][4];
            #pragma unroll
            for (int mt = 0; mt < 2; ++mt)
                ldsm4(a[mt], xs_b +
                      2u * ((wm * 32 + mt * 16 + aro) * XPH + kb + kco));
            #pragma unroll
            for (int hf = 0; hf < 2; ++hf) {
                uint32_t b[2][4];
                #pragma unroll
                for (int p = 0; p < 2; ++p) {
                    int np = hf * 2 + p;
                    ldsm4t(b[p], ws_b +
                           2u * ((kb + aro) * WPH + wn * 64 + np * 16 + kco));
                }
                #pragma unroll
                for (int mt = 0; mt < 2; ++mt)
                    #pragma unroll
                    for (int q = 0; q < 4; ++q)
                        mma16(c[mt][hf * 4 + q], a[mt],
                              b[q >> 1][(q & 1) * 2], b[q >> 1][(q & 1) * 2 + 1]);
            }
        }

        // ---- epilogue ----
        if (b2) {
            #pragma unroll
            for (int mt = 0; mt < 2; ++mt)
                #pragma unroll
                for (int nt = 0; nt < 8; ++nt) {
                    int col = wn * 64 + nt * 8 + tq * 2;
                    float2 bv = *(const float2*)(b2 + col);
                    c[mt][nt][0] += bv.x; c[mt][nt][1] += bv.y;
                    c[mt][nt][2] += bv.x; c[mt][nt][3] += bv.y;
                    if (reluLN) {
                        c[mt][nt][0] = fmaxf(c[mt][nt][0], 0.f);
                        c[mt][nt][1] = fmaxf(c[mt][nt][1], 0.f);
                        c[mt][nt][2] = fmaxf(c[mt][nt][2], 0.f);
                        c[mt][nt][3] = fmaxf(c[mt][nt][3], 0.f);
                    }
                }
        }

        if (doLN) {
            // fragment LN reduction
            float s[2][2], ss[2][2];
            #pragma unroll
            for (int mt = 0; mt < 2; ++mt)
                #pragma unroll
                for (int hf = 0; hf < 2; ++hf) {
                    float a = 0.f, b = 0.f;
                    #pragma unroll
                    for (int nt = 0; nt < 8; ++nt) {
                        float v0 = c[mt][nt][hf * 2];
                        float v1 = c[mt][nt][hf * 2 + 1];
                        a += v0 + v1;
                        b += v0 * v0 + v1 * v1;
                    }
                    #pragma unroll
                    for (int o = 1; o <= 2; o <<= 1) {
                        a += __shfl_xor_sync(0xffffffffu, a, o);
                        b += __shfl_xor_sync(0xffffffffu, b, o);
                    }
                    s[mt][hf] = a;
                    ss[mt][hf] = b;
                }
            if (tq == 0) {
                #pragma unroll
                for (int mt = 0; mt < 2; ++mt)
                    #pragma unroll
                    for (int hf = 0; hf < 2; ++hf) {
                        int row = wm * 32 + mt * 16 + hf * 8 + g;
                        part[row * 4 + wn] = make_float2(s[mt][hf], ss[mt][hf]);
                    }
            }
            __syncthreads();
            #pragma unroll
            for (int mt = 0; mt < 2; ++mt)
                #pragma unroll
                for (int hf = 0; hf < 2; ++hf) {
                    int row = wm * 32 + mt * 16 + hf * 8 + g;
                    float2 p0 = part[row * 4 + 0];
                    float2 p1 = part[row * 4 + 1];
                    float2 p2 = part[row * 4 + 2];
                    float2 p3 = part[row * 4 + 3];
                    float sum = p0.x + p1.x + p2.x + p3.x;
                    float sq  = p0.y + p1.y + p2.y + p3.y;
                    float mean = sum * (1.f / 256.f);
                    float var  = sq * (1.f / 256.f) - mean * mean;
                    float rstd = rsqrtf(var + 1e-5f);
                    long grow = blockRow + row;
                    if (grow < M) {
                        #pragma unroll
                        for (int nt = 0; nt < 8; ++nt) {
                            int col = wn * 64 + nt * 8 + tq * 2;
                            float2 gv = *(const float2*)(lng + col);
                            float2 bv = *(const float2*)(lnb + col);
                            float o0 = (c[mt][nt][hf * 2]     - mean) * rstd * gv.x + bv.x;
                            float o1 = (c[mt][nt][hf * 2 + 1] - mean) * rstd * gv.y + bv.y;
                            if (OutF) {
                                float2 t2 = {o0, o1};
                                *(float2*)(OutF + grow * 256 + col) = t2;
                            } else {
                                __half2 h = __floats2half2_rn(o0, o1);
                                *(uint32_t*)(OutH + grow * 256 + col) = *(uint32_t*)&h;
                            }
                        }
                    }
                }
        } else {
            // plain half store
            #pragma unroll
            for (int mt = 0; mt < 2; ++mt) {
                long rb = blockRow + wm * 32 + mt * 16;
                long r0 = rb + g;
                long r1 = rb + 8 + g;
                #pragma unroll
                for (int nt = 0; nt < 8; ++nt) {
                    int col = wn * 64 + nt * 8 + tq * 2;
                    if (r0 < M) {
                        __half2 h = __floats2half2_rn(c[mt][nt][0], c[mt][nt][1]);
                        *(uint32_t*)(OutH + r0 * 256 + col) = *(uint32_t*)&h;
                    }
                    if (r1 < M) {
                        __half2 h = __floats2half2_rn(c[mt][nt][2], c[mt][nt][3]);
                        *(uint32_t*)(OutH + r1 * 256 + col) = *(uint32_t*)&h;
                    }
                }
            }
        }
        __syncthreads();   // XS/part reads done before next tile's stage
    }
}

// --------------------------------- driver ---------------------------------

extern "C" void kernel_launch(void* const* d_in, const int* in_sizes, int n_in,
                              void* d_out, int out_size) {
    const int*   xcat = (const int*)d_in[0];
    const int*   ei   = (const int*)d_in[1];
    const float* e0   = (const float*)d_in[2];
    const float* e1   = (const float*)d_in[3];
    const float* e2   = (const float*)d_in[4];
    const float* e3   = (const float*)d_in[5];
    const float* w1a  = (const float*)d_in[6];
    const float* b1a  = (const float*)d_in[7];
    const float* w1b  = (const float*)d_in[8];
    const float* b1b  = (const float*)d_in[9];
    const float* w2a  = (const float*)d_in[10];
    const float* b2a  = (const float*)d_in[11];
    const float* w2b  = (const float*)d_in[12];
    const float* b2b  = (const float*)d_in[13];
    const float* ln1g = (const float*)d_in[14];
    const float* ln1b = (const float*)d_in[15];
    const float* ln2g = (const float*)d_in[16];
    const float* ln2b = (const float*)d_in[17];

    int M = in_sizes[0] / 4;
    int E = in_sizes[1] / 2;
    int V = in_sizes[2] / 64;

    __half *h0, *h1, *tabh;
    int *deg, *rowptr, *cursor, *csr;
    cudaGetSymbolAddress((void**)&h0, g_h0);
    cudaGetSymbolAddress((void**)&h1, g_h1);
    cudaGetSymbolAddress((void**)&tabh, g_tabh);
    cudaGetSymbolAddress((void**)&deg, g_deg);
    cudaGetSymbolAddress((void**)&rowptr, g_rowptr);
    cudaGetSymbolAddress((void**)&cursor, g_cursor);
    cudaGetSymbolAddress((void**)&csr, g_csr);

    cudaFuncSetAttribute(k_pgemm, cudaFuncAttributeMaxDynamicSharedMemorySize,
                         PG_SMEM_BYTES);

    int nsm = 0;
    cudaDeviceGetAttribute(&nsm, cudaDevAttrMultiProcessorCount, 0);
    if (nsm <= 0) nsm = 148;

    int rowGrid = (M + 7) / 8;
    int nTiles = (M + 63) / 64;
    int pg = nsm < nTiles ? nsm : nTiles;

    // CSR by dst
    cudaMemsetAsync(deg, 0, (size_t)M * sizeof(int), 0);
    k_count4<<<(E / 4 + 255) / 256, 256>>>(ei, deg, E);
    k_scan<<<1, 1024>>>(deg, rowptr, cursor, M);
    k_fill4<<<(E / 4 + 255) / 256, 256>>>(ei, cursor, csr, E);

    // tables (half) + z0 (half)
    dim3 tgrid((V + 15) / 16, 4);
    k_tab<<<tgrid, 256>>>(e0, e1, e2, e3, w1a, tabh, V);
    k_z0<<<(M * 32 + 255) / 256, 256>>>(xcat, tabh, h0, M);

    // conv1: a1 = agg(z0) -> h1
    k_agg<<<rowGrid, 256>>>(h0, h1, rowptr, csr, M);
    // kG1: h = LN1(relu(relu(a1+b1a)@W1b+b1b)) -> h0
    k_pgemm<<<pg, 256, PG_SMEM_BYTES>>>(h1, b1a, w1b, b1b, ln1g, ln1b,
                                        h0, nullptr, M, nTiles, 1, 1);
    // kG2: u = h@W2a -> h1
    k_pgemm<<<pg, 256, PG_SMEM_BYTES>>>(h0, nullptr, w2a, nullptr,
                                        nullptr, nullptr,
                                        h1, nullptr, M, nTiles, 0, 0);
    // conv2: a2 = agg(u) -> h0
    k_agg<<<rowGrid, 256>>>(h1, h0, rowptr, csr, M);
    // kG3: out = LN2(relu(a2+b2a)@W2b+b2b) -> d_out (fp32)
    k_pgemm<<<pg, 256, PG_SMEM_BYTES>>>(h0, b2a, w2b, b2b, ln2g, ln2b,
                                        nullptr, (float*)d_out, M, nTiles, 0, 1);
}

// round 9
// speedup vs baseline: 1.0683x; 1.0683x over previous
#include <cuda_runtime.h>
#include <cuda_fp16.h>
#include <cstdint>

// ---------------------------------------------------------------------------
// CategoricalGINEncoder on GB300 (sm_103a) — round 9
//  = round 7 (best structure: standalone agg + fused conv, 2 CTAs/SM)
//  + cp.async (LDGSTS) 3-slot ring for W chunks (no RF staging, 1 barrier/chunk)
//  + higher-occupancy k_tab (8 values/block)
// ---------------------------------------------------------------------------

#define NMAX 100000
#define EMAX 1600000
#define DIM  256

__device__ __half g_h0[(size_t)NMAX * DIM];
__device__ __half g_h1[(size_t)NMAX * DIM];
__device__ __half g_tabh[(size_t)4 * 1024 * DIM];
__device__ __align__(256) __half g_w1b[DIM * DIM];
__device__ __align__(256) __half g_w2a[DIM * DIM];
__device__ __align__(256) __half g_w2b[DIM * DIM];
__device__ int    g_deg[NMAX];
__device__ int    g_rowptr[NMAX + 1];
__device__ int    g_cursor[NMAX];
__device__ int    g_csr[EMAX];

// --------------------------- weight conversion ------------------------------

__global__ void k_cvt(const float* __restrict__ src, __half* __restrict__ dst,
                      int n) {
    int i = (blockIdx.x * blockDim.x + threadIdx.x) * 8;
    if (i >= n) return;
    float4 a = *(const float4*)(src + i);
    float4 b = *(const float4*)(src + i + 4);
    __half2 h0 = __floats2half2_rn(a.x, a.y);
    __half2 h1 = __floats2half2_rn(a.z, a.w);
    __half2 h2 = __floats2half2_rn(b.x, b.y);
    __half2 h3 = __floats2half2_rn(b.z, b.w);
    uint4 o;
    o.x = *(uint32_t*)&h0; o.y = *(uint32_t*)&h1;
    o.z = *(uint32_t*)&h2; o.w = *(uint32_t*)&h3;
    *(uint4*)(dst + i) = o;
}

// ------------------------------- CSR build --------------------------------

__global__ void k_count4(const int* __restrict__ ei, int* __restrict__ deg,
                         int E) {
    int i = (blockIdx.x * blockDim.x + threadIdx.x) * 4;
    if (i >= E) return;
    if (i + 3 < E) {
        int4 d = *(const int4*)(ei + E + i);
        atomicAdd(&deg[d.x], 1);
        atomicAdd(&deg[d.y], 1);
        atomicAdd(&deg[d.z], 1);
        atomicAdd(&deg[d.w], 1);
    } else {
        for (; i < E; ++i) atomicAdd(&deg[ei[E + i]], 1);
    }
}

__global__ void k_scan(const int* __restrict__ deg, int* __restrict__ rowptr,
                       int* __restrict__ cursor, int n) {
    __shared__ int sh[1024];
    int t = threadIdx.x;
    int chunk = (n + 1023) >> 10;
    int lo = t * chunk;
    int hi = min(lo + chunk, n);
    int s = 0;
    for (int i = lo; i < hi; ++i) s += deg[i];
    sh[t] = s;
    __syncthreads();
    for (int off = 1; off < 1024; off <<= 1) {
        int v = (t >= off) ? sh[t - off] : 0;
        __syncthreads();
        sh[t] += v;
        __syncthreads();
    }
    int run = (t == 0) ? 0 : sh[t - 1];
    for (int i = lo; i < hi; ++i) {
        rowptr[i] = run;
        cursor[i] = run;
        run += deg[i];
    }
    if (lo < n && hi == n) rowptr[n] = run;
}

__global__ void k_fill4(const int* __restrict__ ei, int* __restrict__ cursor,
                        int* __restrict__ csr, int E) {
    int i = (blockIdx.x * blockDim.x + threadIdx.x) * 4;
    if (i >= E) return;
    if (i + 3 < E) {
        int4 s = *(const int4*)(ei + i);
        int4 d = *(const int4*)(ei + E + i);
        csr[atomicAdd(&cursor[d.x], 1)] = s.x;
        csr[atomicAdd(&cursor[d.y], 1)] = s.y;
        csr[atomicAdd(&cursor[d.z], 1)] = s.z;
        csr[atomicAdd(&cursor[d.w], 1)] = s.w;
    } else {
        for (; i < E; ++i)
            csr[atomicAdd(&cursor[ei[E + i]], 1)] = ei[i];
    }
}

// ------------------------ embedding tables + z0 -----------------------------
// 8 values per block for occupancy (acc[8], 500 blocks)

__global__ void k_tab(const float* __restrict__ e0, const float* __restrict__ e1,
                      const float* __restrict__ e2, const float* __restrict__ e3,
                      const float* __restrict__ w1a, __half* __restrict__ T,
                      int V) {
    int f = blockIdx.y;
    const float* emb = (f == 0) ? e0 : (f == 1) ? e1 : (f == 2) ? e2 : e3;
    int v0 = blockIdx.x * 8;
    __shared__ float es[8 * 64];
    int tid = threadIdx.x;
    #pragma unroll
    for (int i = 0; i < 2; ++i) {
        int idx = i * 256 + tid;
        int v = idx >> 6, k = idx & 63;
        es[idx] = (v0 + v < V) ? emb[(v0 + v) * 64 + k] : 0.f;
    }
    __syncthreads();
    float acc[8];
    #pragma unroll
    for (int v = 0; v < 8; ++v) acc[v] = 0.f;
    int c = tid;
    #pragma unroll 8
    for (int k = 0; k < 64; ++k) {
        float w = w1a[(f * 64 + k) * 256 + c];
        #pragma unroll
        for (int v = 0; v < 8; ++v) acc[v] = fmaf(es[v * 64 + k], w, acc[v]);
    }
    #pragma unroll
    for (int v = 0; v < 8; ++v)
        if (v0 + v < V)
            T[((size_t)f * 1024 + v0 + v) * 256 + c] = __float2half_rn(acc[v]);
}

__device__ __forceinline__ void addh8(float* a, uint4 v) {
    float2 f;
    f = __half22float2(*(__half2*)&v.x); a[0] += f.x; a[1] += f.y;
    f = __half22float2(*(__half2*)&v.y); a[2] += f.x; a[3] += f.y;
    f = __half22float2(*(__half2*)&v.z); a[4] += f.x; a[5] += f.y;
    f = __half22float2(*(__half2*)&v.w); a[6] += f.x; a[7] += f.y;
}

__global__ void k_z0(const int* __restrict__ xc, const __half* __restrict__ T,
                     __half* __restrict__ Z, int M) {
    int idx = blockIdx.x * blockDim.x + threadIdx.x;
    if (idx >= M * 32) return;
    int node = idx >> 5;
    int q = idx & 31;
    int c0 = xc[node * 4 + 0];
    int c1 = xc[node * 4 + 1];
    int c2 = xc[node * 4 + 2];
    int c3 = xc[node * 4 + 3];
    float a[8] = {0.f, 0.f, 0.f, 0.f, 0.f, 0.f, 0.f, 0.f};
    addh8(a, *(const uint4*)(T + ((size_t)0 * 1024 + c0) * 256 + q * 8));
    addh8(a, *(const uint4*)(T + ((size_t)1 * 1024 + c1) * 256 + q * 8));
    addh8(a, *(const uint4*)(T + ((size_t)2 * 1024 + c2) * 256 + q * 8));
    addh8(a, *(const uint4*)(T + ((size_t)3 * 1024 + c3) * 256 + q * 8));
    __half2 h0 = __floats2half2_rn(a[0], a[1]);
    __half2 h1 = __floats2half2_rn(a[2], a[3]);
    __half2 h2 = __floats2half2_rn(a[4], a[5]);
    __half2 h3 = __floats2half2_rn(a[6], a[7]);
    uint4 o;
    o.x = *(uint32_t*)&h0; o.y = *(uint32_t*)&h1;
    o.z = *(uint32_t*)&h2; o.w = *(uint32_t*)&h3;
    ((uint4*)(Z + (size_t)node * 256))[q] = o;
}

// --------------------------- aggregation (half) ----------------------------

__global__ void k_agg(const __half* __restrict__ X, __half* __restrict__ Y,
                      const int* __restrict__ rowptr, const int* __restrict__ csr,
                      int M) {
    int w = (blockIdx.x * blockDim.x + threadIdx.x) >> 5;
    int lane = threadIdx.x & 31;
    if (w >= M) return;
    float a[8] = {0.f, 0.f, 0.f, 0.f, 0.f, 0.f, 0.f, 0.f};
    addh8(a, ((const uint4*)(X + (size_t)w * DIM))[lane]);
    int e = rowptr[w], end = rowptr[w + 1];
    for (; e + 1 < end; e += 2) {
        int s0 = csr[e];
        int s1 = csr[e + 1];
        uint4 u = ((const uint4*)(X + (size_t)s0 * DIM))[lane];
        uint4 v = ((const uint4*)(X + (size_t)s1 * DIM))[lane];
        addh8(a, u);
        addh8(a, v);
    }
    if (e < end) {
        int s = csr[e];
        addh8(a, ((const uint4*)(X + (size_t)s * DIM))[lane]);
    }
    __half2 h0 = __floats2half2_rn(a[0], a[1]);
    __half2 h1 = __floats2half2_rn(a[2], a[3]);
    __half2 h2 = __floats2half2_rn(a[4], a[5]);
    __half2 h3 = __floats2half2_rn(a[6], a[7]);
    uint4 o;
    o.x = *(uint32_t*)&h0; o.y = *(uint32_t*)&h1;
    o.z = *(uint32_t*)&h2; o.w = *(uint32_t*)&h3;
    ((uint4*)(Y + (size_t)w * DIM))[lane] = o;
}

// ------------------------------ fused conv ---------------------------------

#define XPH  264                    // XS row pitch (halves)
#define XS_H (64 * XPH)             // 16896 halves
#define WPH  264                    // W chunk row pitch (halves)
#define W_CH (32 * WPH)             // 8448 halves per chunk
// XS + 3-slot W ring + LN partials
#define CONV_SMEM_BYTES ((XS_H + 3 * W_CH) * 2 + 64 * 4 * 8)   // 86528 B

__device__ __forceinline__ void ldsm4(uint32_t* r, uint32_t addr) {
    asm volatile("ldmatrix.sync.aligned.m8n8.x4.shared.b16 {%0,%1,%2,%3},[%4];"
                 : "=r"(r[0]), "=r"(r[1]), "=r"(r[2]), "=r"(r[3]) : "r"(addr));
}
__device__ __forceinline__ void ldsm4t(uint32_t* r, uint32_t addr) {
    asm volatile("ldmatrix.sync.aligned.m8n8.x4.trans.shared.b16 {%0,%1,%2,%3},[%4];"
                 : "=r"(r[0]), "=r"(r[1]), "=r"(r[2]), "=r"(r[3]) : "r"(addr));
}
__device__ __forceinline__ void mma16(float* c, const uint32_t* a,
                                      uint32_t b0, uint32_t b1) {
    asm volatile(
        "mma.sync.aligned.m16n8k16.row.col.f32.f16.f16.f32 "
        "{%0,%1,%2,%3},{%4,%5,%6,%7},{%8,%9},{%0,%1,%2,%3};\n"
        : "+f"(c[0]), "+f"(c[1]), "+f"(c[2]), "+f"(c[3])
        : "r"(a[0]), "r"(a[1]), "r"(a[2]), "r"(a[3]), "r"(b0), "r"(b1));
}
__device__ __forceinline__ void cp16(uint32_t dst, const void* src) {
    asm volatile("cp.async.cg.shared.global [%0], [%1], 16;\n"
                 :: "r"(dst), "l"(src));
}

// C += XS(64x256 f16) @ W(256x256 f16).
// W streamed via cp.async into a 3-slot smem ring, prefetch distance 2,
// ONE wait_group+syncthreads per 32-k chunk; no RF staging.
__device__ __forceinline__ void gemm_h(
    const __half* __restrict__ W,
    uint32_t xs_b, uint32_t ws_b,
    float (&c)[2][8][4], int tid, int wm, int wn, int lane) {
    const int krow = tid >> 5;                    // 0..7
    const int n8 = tid & 31;                      // 8-half col slot
    const int aro = ((lane >> 3) & 1) * 8 + (lane & 7);
    const int kco = (lane >> 4) * 8;

#define ISSUE_W(ck, s) do {                                                   \
        const __half* _src = W + (size_t)(ck) * 32 * 256;                     \
        uint32_t _dst = ws_b + 2u * (uint32_t)((s) * W_CH);                   \
        _Pragma("unroll")                                                     \
        for (int _i = 0; _i < 4; ++_i) {                                      \
            int _row = krow + _i * 8;                                         \
            cp16(_dst + 2u * (uint32_t)(_row * WPH + n8 * 8),                 \
                 _src + (size_t)_row * 256 + n8 * 8);                         \
        }                                                                     \
        asm volatile("cp.async.commit_group;");                               \
    } while (0)

    ISSUE_W(0, 0);
    ISSUE_W(1, 1);

    #pragma unroll 1
    for (int it = 0; it < 8; ++it) {
        if (it < 7) asm volatile("cp.async.wait_group 1;");
        else        asm volatile("cp.async.wait_group 0;");
        __syncthreads();          // chunk 'it' visible to all; slot (it+2)%3 free
        if (it < 6) {
            int s = (it + 2) % 3;
            ISSUE_W(it + 2, s);
        }
        uint32_t wsb = ws_b + 2u * (uint32_t)((it % 3) * W_CH);
        #pragma unroll
        for (int kt = 0; kt < 2; ++kt) {
            const int ktb = it * 32 + kt * 16;    // k in XS
            const int ktL = kt * 16;              // k in chunk
            uint32_t a[2][4];
            #pragma unroll
            for (int mt = 0; mt < 2; ++mt)
                ldsm4(a[mt], xs_b +
                      2u * ((wm * 32 + mt * 16 + aro) * XPH + ktb + kco));
            #pragma unroll
            for (int hf = 0; hf < 2; ++hf) {
                uint32_t b[2][4];
                #pragma unroll
                for (int p = 0; p < 2; ++p) {
                    int np = hf * 2 + p;
                    ldsm4t(b[p], wsb +
                           2u * ((ktL + aro) * WPH + wn * 64 + np * 16 + kco));
                }
                #pragma unroll
                for (int mt = 0; mt < 2; ++mt)
                    #pragma unroll
                    for (int q = 0; q < 4; ++q)
                        mma16(c[mt][hf * 4 + q], a[mt],
                              b[q >> 1][(q & 1) * 2], b[q >> 1][(q & 1) * 2 + 1]);
            }
        }
    }
#undef ISSUE_W
}

__global__ void __launch_bounds__(256, 2) k_conv(
    const __half* __restrict__ A,  const float* __restrict__ bIn,
    const __half* __restrict__ W1, const float* __restrict__ b1,
    const float* __restrict__ lng, const float* __restrict__ lnb,
    const __half* __restrict__ W2,
    __half* __restrict__ OutH, float* __restrict__ OutF,
    int M, int reluLN, int hasG2) {
    extern __shared__ __half smh[];
    __half* XS = smh;
    float2* part = (float2*)(smh + XS_H + 3 * W_CH);   // [64][4]

    const int tid  = threadIdx.x;
    const int warp = tid >> 5, lane = tid & 31;
    const int wm = warp >> 2;
    const int wn = warp & 3;
    const int g  = lane >> 2;
    const int tq = lane & 3;
    const long blockRow = (long)blockIdx.x * 64;
    uint32_t xs_b = (uint32_t)__cvta_generic_to_shared(XS);
    uint32_t ws_b = (uint32_t)__cvta_generic_to_shared(smh + XS_H);

    // ---- stage: XS = half( relu(A + bIn) ) ----
    #pragma unroll
    for (int i = 0; i < 8; ++i) {
        int id = i * 256 + tid;        // 2048 uint4 total
        int row = id >> 5;
        int q = id & 31;
        long r = blockRow + row;
        if (r > M - 1) r = M - 1;
        uint4 v = ((const uint4*)(A + r * 256))[q];
        float4 ba = *(const float4*)(bIn + q * 8);
        float4 bb = *(const float4*)(bIn + q * 8 + 4);
        float f[8];
        float2 t;
        t = __half22float2(*(__half2*)&v.x); f[0] = t.x; f[1] = t.y;
        t = __half22float2(*(__half2*)&v.y); f[2] = t.x; f[3] = t.y;
        t = __half22float2(*(__half2*)&v.z); f[4] = t.x; f[5] = t.y;
        t = __half22float2(*(__half2*)&v.w); f[6] = t.x; f[7] = t.y;
        f[0] = fmaxf(f[0] + ba.x, 0.f); f[1] = fmaxf(f[1] + ba.y, 0.f);
        f[2] = fmaxf(f[2] + ba.z, 0.f); f[3] = fmaxf(f[3] + ba.w, 0.f);
        f[4] = fmaxf(f[4] + bb.x, 0.f); f[5] = fmaxf(f[5] + bb.y, 0.f);
        f[6] = fmaxf(f[6] + bb.z, 0.f); f[7] = fmaxf(f[7] + bb.w, 0.f);
        __half2 h0 = __floats2half2_rn(f[0], f[1]);
        __half2 h1 = __floats2half2_rn(f[2], f[3]);
        __half2 h2 = __floats2half2_rn(f[4], f[5]);
        __half2 h3 = __floats2half2_rn(f[6], f[7]);
        uint4 o;
        o.x = *(uint32_t*)&h0; o.y = *(uint32_t*)&h1;
        o.z = *(uint32_t*)&h2; o.w = *(uint32_t*)&h3;
        *(uint4*)(XS + row * XPH + q * 8) = o;
    }

    float c[2][8][4];
    #pragma unroll
    for (int i = 0; i < 2; ++i)
        #pragma unroll
        for (int j = 0; j < 8; ++j)
            #pragma unroll
            for (int k = 0; k < 4; ++k) c[i][j][k] = 0.f;

    gemm_h(W1, xs_b, ws_b, c, tid, wm, wn, lane);

    // ---- epilogue: bias (+relu) in regs ----
    #pragma unroll
    for (int mt = 0; mt < 2; ++mt)
        #pragma unroll
        for (int nt = 0; nt < 8; ++nt) {
            int col = wn * 64 + nt * 8 + tq * 2;
            float2 bv = *(const float2*)(b1 + col);
            c[mt][nt][0] += bv.x; c[mt][nt][1] += bv.y;
            c[mt][nt][2] += bv.x; c[mt][nt][3] += bv.y;
            if (reluLN) {
                c[mt][nt][0] = fmaxf(c[mt][nt][0], 0.f);
                c[mt][nt][1] = fmaxf(c[mt][nt][1], 0.f);
                c[mt][nt][2] = fmaxf(c[mt][nt][2], 0.f);
                c[mt][nt][3] = fmaxf(c[mt][nt][3], 0.f);
            }
        }

    // ---- LN: fragment reduction ----
    float s[2][2], ss[2][2];
    #pragma unroll
    for (int mt = 0; mt < 2; ++mt)
        #pragma unroll
        for (int hf = 0; hf < 2; ++hf) {
            float a = 0.f, b = 0.f;
            #pragma unroll
            for (int nt = 0; nt < 8; ++nt) {
                float v0 = c[mt][nt][hf * 2];
                float v1 = c[mt][nt][hf * 2 + 1];
                a += v0 + v1;
                b += v0 * v0 + v1 * v1;
            }
            #pragma unroll
            for (int o = 1; o <= 2; o <<= 1) {
                a += __shfl_xor_sync(0xffffffffu, a, o);
                b += __shfl_xor_sync(0xffffffffu, b, o);
            }
            s[mt][hf] = a;
            ss[mt][hf] = b;
        }
    if (tq == 0) {
        #pragma unroll
        for (int mt = 0; mt < 2; ++mt)
            #pragma unroll
            for (int hf = 0; hf < 2; ++hf) {
                int row = wm * 32 + mt * 16 + hf * 8 + g;
                part[row * 4 + wn] = make_float2(s[mt][hf], ss[mt][hf]);
            }
    }
    __syncthreads();   // also separates GEMM1's XS reads from XS writes below

    #pragma unroll
    for (int mt = 0; mt < 2; ++mt)
        #pragma unroll
        for (int hf = 0; hf < 2; ++hf) {
            int row = wm * 32 + mt * 16 + hf * 8 + g;
            float2 p0 = part[row * 4 + 0];
            float2 p1 = part[row * 4 + 1];
            float2 p2 = part[row * 4 + 2];
            float2 p3 = part[row * 4 + 3];
            float sum = p0.x + p1.x + p2.x + p3.x;
            float sq  = p0.y + p1.y + p2.y + p3.y;
            float mean = sum * (1.f / 256.f);
            float var  = sq * (1.f / 256.f) - mean * mean;
            float rstd = rsqrtf(var + 1e-5f);
            long grow = blockRow + row;
            #pragma unroll
            for (int nt = 0; nt < 8; ++nt) {
                int col = wn * 64 + nt * 8 + tq * 2;
                float2 gv = *(const float2*)(lng + col);
                float2 bv = *(const float2*)(lnb + col);
                float o0 = (c[mt][nt][hf * 2]     - mean) * rstd * gv.x + bv.x;
                float o1 = (c[mt][nt][hf * 2 + 1] - mean) * rstd * gv.y + bv.y;
                if (hasG2) {
                    __half2 h = __floats2half2_rn(o0, o1);
                    *(uint32_t*)(XS + row * XPH + col) = *(uint32_t*)&h;
                } else if (grow < M) {
                    float2 t = {o0, o1};
                    *(float2*)(OutF + grow * 256 + col) = t;
                }
            }
        }
    if (!hasG2) return;
    __syncthreads();   // XS writes visible before GEMM2 reads

    // ---- GEMM2: u = h @ W2 (no bias), store half ----
    #pragma unroll
    for (int i = 0; i < 2; ++i)
        #pragma unroll
        for (int j = 0; j < 8; ++j)
            #pragma unroll
            for (int k = 0; k < 4; ++k) c[i][j][k] = 0.f;

    gemm_h(W2, xs_b, ws_b, c, tid, wm, wn, lane);

    #pragma unroll
    for (int mt = 0; mt < 2; ++mt) {
        long rb = blockRow + wm * 32 + mt * 16;
        long r0 = rb + g;
        long r1 = rb + 8 + g;
        #pragma unroll
        for (int nt = 0; nt < 8; ++nt) {
            int col = wn * 64 + nt * 8 + tq * 2;
            if (r0 < M) {
                __half2 h = __floats2half2_rn(c[mt][nt][0], c[mt][nt][1]);
                *(uint32_t*)(OutH + r0 * 256 + col) = *(uint32_t*)&h;
            }
            if (r1 < M) {
                __half2 h = __floats2half2_rn(c[mt][nt][2], c[mt][nt][3]);
                *(uint32_t*)(OutH + r1 * 256 + col) = *(uint32_t*)&h;
            }
        }
    }
}

// --------------------------------- driver ---------------------------------

extern "C" void kernel_launch(void* const* d_in, const int* in_sizes, int n_in,
                              void* d_out, int out_size) {
    const int*   xcat = (const int*)d_in[0];
    const int*   ei   = (const int*)d_in[1];
    const float* e0   = (const float*)d_in[2];
    const float* e1   = (const float*)d_in[3];
    const float* e2   = (const float*)d_in[4];
    const float* e3   = (const float*)d_in[5];
    const float* w1a  = (const float*)d_in[6];
    const float* b1a  = (const float*)d_in[7];
    const float* w1b  = (const float*)d_in[8];
    const float* b1b  = (const float*)d_in[9];
    const float* w2a  = (const float*)d_in[10];
    const float* b2a  = (const float*)d_in[11];
    const float* w2b  = (const float*)d_in[12];
    const float* b2b  = (const float*)d_in[13];
    const float* ln1g = (const float*)d_in[14];
    const float* ln1b = (const float*)d_in[15];
    const float* ln2g = (const float*)d_in[16];
    const float* ln2b = (const float*)d_in[17];

    int M = in_sizes[0] / 4;
    int E = in_sizes[1] / 2;
    int V = in_sizes[2] / 64;

    __half *h0, *h1, *tabh, *hw1b, *hw2a, *hw2b;
    int *deg, *rowptr, *cursor, *csr;
    cudaGetSymbolAddress((void**)&h0, g_h0);
    cudaGetSymbolAddress((void**)&h1, g_h1);
    cudaGetSymbolAddress((void**)&tabh, g_tabh);
    cudaGetSymbolAddress((void**)&hw1b, g_w1b);
    cudaGetSymbolAddress((void**)&hw2a, g_w2a);
    cudaGetSymbolAddress((void**)&hw2b, g_w2b);
    cudaGetSymbolAddress((void**)&deg, g_deg);
    cudaGetSymbolAddress((void**)&rowptr, g_rowptr);
    cudaGetSymbolAddress((void**)&cursor, g_cursor);
    cudaGetSymbolAddress((void**)&csr, g_csr);

    cudaFuncSetAttribute(k_conv, cudaFuncAttributeMaxDynamicSharedMemorySize,
                         CONV_SMEM_BYTES);

    int rowGrid = (M + 7) / 8;
    int convGrid = (M + 63) / 64;

    // weights -> half (once per call; cheap)
    k_cvt<<<(DIM * DIM / 8 + 255) / 256, 256>>>(w1b, hw1b, DIM * DIM);
    k_cvt<<<(DIM * DIM / 8 + 255) / 256, 256>>>(w2a, hw2a, DIM * DIM);
    k_cvt<<<(DIM * DIM / 8 + 255) / 256, 256>>>(w2b, hw2b, DIM * DIM);

    // CSR by dst
    cudaMemsetAsync(deg, 0, (size_t)M * sizeof(int), 0);
    k_count4<<<(E / 4 + 255) / 256, 256>>>(ei, deg, E);
    k_scan<<<1, 1024>>>(deg, rowptr, cursor, M);
    k_fill4<<<(E / 4 + 255) / 256, 256>>>(ei, cursor, csr, E);

    // tables (half) + z0 (half)
    dim3 tgrid((V + 7) / 8, 4);
    k_tab<<<tgrid, 256>>>(e0, e1, e2, e3, w1a, tabh, V);
    k_z0<<<(M * 32 + 255) / 256, 256>>>(xcat, tabh, h0, M);

    // conv1: a1 = agg(z0); h = LN1(relu(relu(a1+b1a)@W1b+b1b)); u = h@W2a
    k_agg<<<rowGrid, 256>>>(h0, h1, rowptr, csr, M);
    k_conv<<<convGrid, 256, CONV_SMEM_BYTES>>>(h1, b1a, hw1b, b1b, ln1g, ln1b,
                                               hw2a, h0, nullptr, M, 1, 1);

    // conv2: a2 = agg(u); out = LN2(relu(a2+b2a)@W2b+b2b)
    k_agg<<<rowGrid, 256>>>(h0, h1, rowptr, csr, M);
    k_conv<<<convGrid, 256, CONV_SMEM_BYTES>>>(h1, b2a, hw2b, b2b, ln2g, ln2b,
                                               nullptr, nullptr, (float*)d_out,
                                               M, 0, 0);
}

// round 10
// speedup vs baseline: 1.1005x; 1.0301x over previous
#include <cuda_runtime.h>
#include <cuda_fp16.h>
#include <cstdint>

// ---------------------------------------------------------------------------
// CategoricalGINEncoder on GB300 (sm_103a) — round 10
//  = round 9 (fp16 datapath, cp.async W ring, 2 CTAs/SM conv)
//  + independent launch chains fused into block-partitioned kernels:
//      k_front1 = CSR-count || emb-table build || weight cvt
//      k_front2 = CSR-fill  || z0 lookup-sum
//    (same-stream graph nodes serialize; one kernel's blocks overlap freely)
// ---------------------------------------------------------------------------

#define NMAX 100000
#define EMAX 1600000
#define DIM  256

__device__ __half g_h0[(size_t)NMAX * DIM];
__device__ __half g_h1[(size_t)NMAX * DIM];
__device__ __half g_tabh[(size_t)4 * 1024 * DIM];
__device__ __align__(256) __half g_w1b[DIM * DIM];
__device__ __align__(256) __half g_w2a[DIM * DIM];
__device__ __align__(256) __half g_w2b[DIM * DIM];
__device__ int    g_deg[NMAX];
__device__ int    g_rowptr[NMAX + 1];
__device__ int    g_cursor[NMAX];
__device__ int    g_csr[EMAX];

// ------------------------------ front kernel 1 ------------------------------
// blocks [0, nCnt)           : CSR degree count (4 edges/thread, atomics)
// blocks [nCnt, nCnt+4*nVb)  : T_f = emb_f @ W1a_f  (half table)
// blocks [.., +nCvt)         : fp32->half weight conversion (3 matrices)

__global__ void k_front1(const int* __restrict__ ei, int* __restrict__ deg, int E,
                         const float* __restrict__ e0, const float* __restrict__ e1,
                         const float* __restrict__ e2, const float* __restrict__ e3,
                         const float* __restrict__ w1a, __half* __restrict__ T, int V,
                         const float* __restrict__ wf1, __half* __restrict__ wh1,
                         const float* __restrict__ wf2, __half* __restrict__ wh2,
                         const float* __restrict__ wf3, __half* __restrict__ wh3,
                         int nCnt, int nVb) {
    __shared__ float es[8 * 64];
    int b = blockIdx.x;
    int tid = threadIdx.x;
    if (b < nCnt) {
        // ---- CSR count ----
        int i = (b * 256 + tid) * 4;
        if (i >= E) return;
        if (i + 3 < E) {
            int4 d = *(const int4*)(ei + E + i);
            atomicAdd(&deg[d.x], 1);
            atomicAdd(&deg[d.y], 1);
            atomicAdd(&deg[d.z], 1);
            atomicAdd(&deg[d.w], 1);
        } else {
            for (; i < E; ++i) atomicAdd(&deg[ei[E + i]], 1);
        }
        return;
    }
    b -= nCnt;
    if (b < 4 * nVb) {
        // ---- embedding table build ----
        int f = b / nVb;
        int v0 = (b % nVb) * 8;
        const float* emb = (f == 0) ? e0 : (f == 1) ? e1 : (f == 2) ? e2 : e3;
        #pragma unroll
        for (int i = 0; i < 2; ++i) {
            int idx = i * 256 + tid;
            int v = idx >> 6, k = idx & 63;
            es[idx] = (v0 + v < V) ? emb[(v0 + v) * 64 + k] : 0.f;
        }
        __syncthreads();
        float acc[8];
        #pragma unroll
        for (int v = 0; v < 8; ++v) acc[v] = 0.f;
        int c = tid;
        #pragma unroll 8
        for (int k = 0; k < 64; ++k) {
            float w = w1a[(f * 64 + k) * 256 + c];
            #pragma unroll
            for (int v = 0; v < 8; ++v) acc[v] = fmaf(es[v * 64 + k], w, acc[v]);
        }
        #pragma unroll
        for (int v = 0; v < 8; ++v)
            if (v0 + v < V)
                T[((size_t)f * 1024 + v0 + v) * 256 + c] = __float2half_rn(acc[v]);
        return;
    }
    b -= 4 * nVb;
    {
        // ---- weight conversion: 2048 elems per block ----
        int idx = b * 2048 + tid * 8;
        const float* src;
        __half* dst;
        int off;
        if (idx < DIM * DIM)            { src = wf1; dst = wh1; off = idx; }
        else if (idx < 2 * DIM * DIM)   { src = wf2; dst = wh2; off = idx - DIM * DIM; }
        else if (idx < 3 * DIM * DIM)   { src = wf3; dst = wh3; off = idx - 2 * DIM * DIM; }
        else return;
        float4 a = *(const float4*)(src + off);
        float4 bb = *(const float4*)(src + off + 4);
        __half2 h0 = __floats2half2_rn(a.x, a.y);
        __half2 h1 = __floats2half2_rn(a.z, a.w);
        __half2 h2 = __floats2half2_rn(bb.x, bb.y);
        __half2 h3 = __floats2half2_rn(bb.z, bb.w);
        uint4 o;
        o.x = *(uint32_t*)&h0; o.y = *(uint32_t*)&h1;
        o.z = *(uint32_t*)&h2; o.w = *(uint32_t*)&h3;
        *(uint4*)(dst + off) = o;
    }
}

// ------------------------------- scan (1 block) -----------------------------

__global__ void k_scan(const int* __restrict__ deg, int* __restrict__ rowptr,
                       int* __restrict__ cursor, int n) {
    __shared__ int sh[1024];
    int t = threadIdx.x;
    int chunk = (n + 1023) >> 10;
    int lo = t * chunk;
    int hi = min(lo + chunk, n);
    int s = 0;
    #pragma unroll 4
    for (int i = lo; i < hi; ++i) s += deg[i];
    sh[t] = s;
    __syncthreads();
    for (int off = 1; off < 1024; off <<= 1) {
        int v = (t >= off) ? sh[t - off] : 0;
        __syncthreads();
        sh[t] += v;
        __syncthreads();
    }
    int run = (t == 0) ? 0 : sh[t - 1];
    for (int i = lo; i < hi; ++i) {
        rowptr[i] = run;
        cursor[i] = run;
        run += deg[i];
    }
    if (lo < n && hi == n) rowptr[n] = run;
}

// ------------------------------ front kernel 2 ------------------------------
// blocks [0, nFill)  : CSR fill
// blocks [nFill, ..) : z0 = half(sum_f T_f[cat_f])

__device__ __forceinline__ void addh8(float* a, uint4 v) {
    float2 f;
    f = __half22float2(*(__half2*)&v.x); a[0] += f.x; a[1] += f.y;
    f = __half22float2(*(__half2*)&v.y); a[2] += f.x; a[3] += f.y;
    f = __half22float2(*(__half2*)&v.z); a[4] += f.x; a[5] += f.y;
    f = __half22float2(*(__half2*)&v.w); a[6] += f.x; a[7] += f.y;
}

__global__ void k_front2(const int* __restrict__ ei, int* __restrict__ cursor,
                         int* __restrict__ csr, int E,
                         const int* __restrict__ xc, const __half* __restrict__ T,
                         __half* __restrict__ Z, int M, int nFill) {
    int b = blockIdx.x;
    int tid = threadIdx.x;
    if (b < nFill) {
        int i = (b * 256 + tid) * 4;
        if (i >= E) return;
        if (i + 3 < E) {
            int4 s = *(const int4*)(ei + i);
            int4 d = *(const int4*)(ei + E + i);
            csr[atomicAdd(&cursor[d.x], 1)] = s.x;
            csr[atomicAdd(&cursor[d.y], 1)] = s.y;
            csr[atomicAdd(&cursor[d.z], 1)] = s.z;
            csr[atomicAdd(&cursor[d.w], 1)] = s.w;
        } else {
            for (; i < E; ++i)
                csr[atomicAdd(&cursor[ei[E + i]], 1)] = ei[i];
        }
        return;
    }
    int idx = (b - nFill) * 256 + tid;
    if (idx >= M * 32) return;
    int node = idx >> 5;
    int q = idx & 31;
    int c0 = xc[node * 4 + 0];
    int c1 = xc[node * 4 + 1];
    int c2 = xc[node * 4 + 2];
    int c3 = xc[node * 4 + 3];
    float a[8] = {0.f, 0.f, 0.f, 0.f, 0.f, 0.f, 0.f, 0.f};
    addh8(a, *(const uint4*)(T + ((size_t)0 * 1024 + c0) * 256 + q * 8));
    addh8(a, *(const uint4*)(T + ((size_t)1 * 1024 + c1) * 256 + q * 8));
    addh8(a, *(const uint4*)(T + ((size_t)2 * 1024 + c2) * 256 + q * 8));
    addh8(a, *(const uint4*)(T + ((size_t)3 * 1024 + c3) * 256 + q * 8));
    __half2 h0 = __floats2half2_rn(a[0], a[1]);
    __half2 h1 = __floats2half2_rn(a[2], a[3]);
    __half2 h2 = __floats2half2_rn(a[4], a[5]);
    __half2 h3 = __floats2half2_rn(a[6], a[7]);
    uint4 o;
    o.x = *(uint32_t*)&h0; o.y = *(uint32_t*)&h1;
    o.z = *(uint32_t*)&h2; o.w = *(uint32_t*)&h3;
    ((uint4*)(Z + (size_t)node * 256))[q] = o;
}

// --------------------------- aggregation (half) ----------------------------

__global__ void k_agg(const __half* __restrict__ X, __half* __restrict__ Y,
                      const int* __restrict__ rowptr, const int* __restrict__ csr,
                      int M) {
    int w = (blockIdx.x * blockDim.x + threadIdx.x) >> 5;
    int lane = threadIdx.x & 31;
    if (w >= M) return;
    float a[8] = {0.f, 0.f, 0.f, 0.f, 0.f, 0.f, 0.f, 0.f};
    addh8(a, ((const uint4*)(X + (size_t)w * DIM))[lane]);
    int e = rowptr[w], end = rowptr[w + 1];
    for (; e + 1 < end; e += 2) {
        int s0 = csr[e];
        int s1 = csr[e + 1];
        uint4 u = ((const uint4*)(X + (size_t)s0 * DIM))[lane];
        uint4 v = ((const uint4*)(X + (size_t)s1 * DIM))[lane];
        addh8(a, u);
        addh8(a, v);
    }
    if (e < end) {
        int s = csr[e];
        addh8(a, ((const uint4*)(X + (size_t)s * DIM))[lane]);
    }
    __half2 h0 = __floats2half2_rn(a[0], a[1]);
    __half2 h1 = __floats2half2_rn(a[2], a[3]);
    __half2 h2 = __floats2half2_rn(a[4], a[5]);
    __half2 h3 = __floats2half2_rn(a[6], a[7]);
    uint4 o;
    o.x = *(uint32_t*)&h0; o.y = *(uint32_t*)&h1;
    o.z = *(uint32_t*)&h2; o.w = *(uint32_t*)&h3;
    ((uint4*)(Y + (size_t)w * DIM))[lane] = o;
}

// ------------------------------ fused conv ---------------------------------

#define XPH  264
#define XS_H (64 * XPH)
#define WPH  264
#define W_CH (32 * WPH)
#define CONV_SMEM_BYTES ((XS_H + 3 * W_CH) * 2 + 64 * 4 * 8)   // 86528 B

__device__ __forceinline__ void ldsm4(uint32_t* r, uint32_t addr) {
    asm volatile("ldmatrix.sync.aligned.m8n8.x4.shared.b16 {%0,%1,%2,%3},[%4];"
                 : "=r"(r[0]), "=r"(r[1]), "=r"(r[2]), "=r"(r[3]) : "r"(addr));
}
__device__ __forceinline__ void ldsm4t(uint32_t* r, uint32_t addr) {
    asm volatile("ldmatrix.sync.aligned.m8n8.x4.trans.shared.b16 {%0,%1,%2,%3},[%4];"
                 : "=r"(r[0]), "=r"(r[1]), "=r"(r[2]), "=r"(r[3]) : "r"(addr));
}
__device__ __forceinline__ void mma16(float* c, const uint32_t* a,
                                      uint32_t b0, uint32_t b1) {
    asm volatile(
        "mma.sync.aligned.m16n8k16.row.col.f32.f16.f16.f32 "
        "{%0,%1,%2,%3},{%4,%5,%6,%7},{%8,%9},{%0,%1,%2,%3};\n"
        : "+f"(c[0]), "+f"(c[1]), "+f"(c[2]), "+f"(c[3])
        : "r"(a[0]), "r"(a[1]), "r"(a[2]), "r"(a[3]), "r"(b0), "r"(b1));
}
__device__ __forceinline__ void cp16(uint32_t dst, const void* src) {
    asm volatile("cp.async.cg.shared.global [%0], [%1], 16;\n"
                 :: "r"(dst), "l"(src));
}

__device__ __forceinline__ void gemm_h(
    const __half* __restrict__ W,
    uint32_t xs_b, uint32_t ws_b,
    float (&c)[2][8][4], int tid, int wm, int wn, int lane) {
    const int krow = tid >> 5;
    const int n8 = tid & 31;
    const int aro = ((lane >> 3) & 1) * 8 + (lane & 7);
    const int kco = (lane >> 4) * 8;

#define ISSUE_W(ck, s) do {                                                   \
        const __half* _src = W + (size_t)(ck) * 32 * 256;                     \
        uint32_t _dst = ws_b + 2u * (uint32_t)((s) * W_CH);                   \
        _Pragma("unroll")                                                     \
        for (int _i = 0; _i < 4; ++_i) {                                      \
            int _row = krow + _i * 8;                                         \
            cp16(_dst + 2u * (uint32_t)(_row * WPH + n8 * 8),                 \
                 _src + (size_t)_row * 256 + n8 * 8);                         \
        }                                                                     \
        asm volatile("cp.async.commit_group;");                               \
    } while (0)

    ISSUE_W(0, 0);
    ISSUE_W(1, 1);

    #pragma unroll 1
    for (int it = 0; it < 8; ++it) {
        if (it < 7) asm volatile("cp.async.wait_group 1;");
        else        asm volatile("cp.async.wait_group 0;");
        __syncthreads();
        if (it < 6) {
            int s = (it + 2) % 3;
            ISSUE_W(it + 2, s);
        }
        uint32_t wsb = ws_b + 2u * (uint32_t)((it % 3) * W_CH);
        #pragma unroll
        for (int kt = 0; kt < 2; ++kt) {
            const int ktb = it * 32 + kt * 16;
            const int ktL = kt * 16;
            uint32_t a[2][4];
            #pragma unroll
            for (int mt = 0; mt < 2; ++mt)
                ldsm4(a[mt], xs_b +
                      2u * ((wm * 32 + mt * 16 + aro) * XPH + ktb + kco));
            #pragma unroll
            for (int hf = 0; hf < 2; ++hf) {
                uint32_t b[2][4];
                #pragma unroll
                for (int p = 0; p < 2; ++p) {
                    int np = hf * 2 + p;
                    ldsm4t(b[p], wsb +
                           2u * ((ktL + aro) * WPH + wn * 64 + np * 16 + kco));
                }
                #pragma unroll
                for (int mt = 0; mt < 2; ++mt)
                    #pragma unroll
                    for (int q = 0; q < 4; ++q)
                        mma16(c[mt][hf * 4 + q], a[mt],
                              b[q >> 1][(q & 1) * 2], b[q >> 1][(q & 1) * 2 + 1]);
            }
        }
    }
#undef ISSUE_W
}

__global__ void __launch_bounds__(256, 2) k_conv(
    const __half* __restrict__ A,  const float* __restrict__ bIn,
    const __half* __restrict__ W1, const float* __restrict__ b1,
    const float* __restrict__ lng, const float* __restrict__ lnb,
    const __half* __restrict__ W2,
    __half* __restrict__ OutH, float* __restrict__ OutF,
    int M, int reluLN, int hasG2) {
    extern __shared__ __half smh[];
    __half* XS = smh;
    float2* part = (float2*)(smh + XS_H + 3 * W_CH);

    const int tid  = threadIdx.x;
    const int warp = tid >> 5, lane = tid & 31;
    const int wm = warp >> 2;
    const int wn = warp & 3;
    const int g  = lane >> 2;
    const int tq = lane & 3;
    const long blockRow = (long)blockIdx.x * 64;
    uint32_t xs_b = (uint32_t)__cvta_generic_to_shared(XS);
    uint32_t ws_b = (uint32_t)__cvta_generic_to_shared(smh + XS_H);

    #pragma unroll
    for (int i = 0; i < 8; ++i) {
        int id = i * 256 + tid;
        int row = id >> 5;
        int q = id & 31;
        long r = blockRow + row;
        if (r > M - 1) r = M - 1;
        uint4 v = ((const uint4*)(A + r * 256))[q];
        float4 ba = *(const float4*)(bIn + q * 8);
        float4 bb = *(const float4*)(bIn + q * 8 + 4);
        float f[8];
        float2 t;
        t = __half22float2(*(__half2*)&v.x); f[0] = t.x; f[1] = t.y;
        t = __half22float2(*(__half2*)&v.y); f[2] = t.x; f[3] = t.y;
        t = __half22float2(*(__half2*)&v.z); f[4] = t.x; f[5] = t.y;
        t = __half22float2(*(__half2*)&v.w); f[6] = t.x; f[7] = t.y;
        f[0] = fmaxf(f[0] + ba.x, 0.f); f[1] = fmaxf(f[1] + ba.y, 0.f);
        f[2] = fmaxf(f[2] + ba.z, 0.f); f[3] = fmaxf(f[3] + ba.w, 0.f);
        f[4] = fmaxf(f[4] + bb.x, 0.f); f[5] = fmaxf(f[5] + bb.y, 0.f);
        f[6] = fmaxf(f[6] + bb.z, 0.f); f[7] = fmaxf(f[7] + bb.w, 0.f);
        __half2 h0 = __floats2half2_rn(f[0], f[1]);
        __half2 h1 = __floats2half2_rn(f[2], f[3]);
        __half2 h2 = __floats2half2_rn(f[4], f[5]);
        __half2 h3 = __floats2half2_rn(f[6], f[7]);
        uint4 o;
        o.x = *(uint32_t*)&h0; o.y = *(uint32_t*)&h1;
        o.z = *(uint32_t*)&h2; o.w = *(uint32_t*)&h3;
        *(uint4*)(XS + row * XPH + q * 8) = o;
    }

    float c[2][8][4];
    #pragma unroll
    for (int i = 0; i < 2; ++i)
        #pragma unroll
        for (int j = 0; j < 8; ++j)
            #pragma unroll
            for (int k = 0; k < 4; ++k) c[i][j][k] = 0.f;

    gemm_h(W1, xs_b, ws_b, c, tid, wm, wn, lane);

    #pragma unroll
    for (int mt = 0; mt < 2; ++mt)
        #pragma unroll
        for (int nt = 0; nt < 8; ++nt) {
            int col = wn * 64 + nt * 8 + tq * 2;
            float2 bv = *(const float2*)(b1 + col);
            c[mt][nt][0] += bv.x; c[mt][nt][1] += bv.y;
            c[mt][nt][2] += bv.x; c[mt][nt][3] += bv.y;
            if (reluLN) {
                c[mt][nt][0] = fmaxf(c[mt][nt][0], 0.f);
                c[mt][nt][1] = fmaxf(c[mt][nt][1], 0.f);
                c[mt][nt][2] = fmaxf(c[mt][nt][2], 0.f);
                c[mt][nt][3] = fmaxf(c[mt][nt][3], 0.f);
            }
        }

    float s[2][2], ss[2][2];
    #pragma unroll
    for (int mt = 0; mt < 2; ++mt)
        #pragma unroll
        for (int hf = 0; hf < 2; ++hf) {
            float a = 0.f, b = 0.f;
            #pragma unroll
            for (int nt = 0; nt < 8; ++nt) {
                float v0 = c[mt][nt][hf * 2];
                float v1 = c[mt][nt][hf * 2 + 1];
                a += v0 + v1;
                b += v0 * v0 + v1 * v1;
            }
            #pragma unroll
            for (int o = 1; o <= 2; o <<= 1) {
                a += __shfl_xor_sync(0xffffffffu, a, o);
                b += __shfl_xor_sync(0xffffffffu, b, o);
            }
            s[mt][hf] = a;
            ss[mt][hf] = b;
        }
    if (tq == 0) {
        #pragma unroll
        for (int mt = 0; mt < 2; ++mt)
            #pragma unroll
            for (int hf = 0; hf < 2; ++hf) {
                int row = wm * 32 + mt * 16 + hf * 8 + g;
                part[row * 4 + wn] = make_float2(s[mt][hf], ss[mt][hf]);
            }
    }
    __syncthreads();

    #pragma unroll
    for (int mt = 0; mt < 2; ++mt)
        #pragma unroll
        for (int hf = 0; hf < 2; ++hf) {
            int row = wm * 32 + mt * 16 + hf * 8 + g;
            float2 p0 = part[row * 4 + 0];
            float2 p1 = part[row * 4 + 1];
            float2 p2 = part[row * 4 + 2];
            float2 p3 = part[row * 4 + 3];
            float sum = p0.x + p1.x + p2.x + p3.x;
            float sq  = p0.y + p1.y + p2.y + p3.y;
            float mean = sum * (1.f / 256.f);
            float var  = sq * (1.f / 256.f) - mean * mean;
            float rstd = rsqrtf(var + 1e-5f);
            long grow = blockRow + row;
            #pragma unroll
            for (int nt = 0; nt < 8; ++nt) {
                int col = wn * 64 + nt * 8 + tq * 2;
                float2 gv = *(const float2*)(lng + col);
                float2 bv = *(const float2*)(lnb + col);
                float o0 = (c[mt][nt][hf * 2]     - mean) * rstd * gv.x + bv.x;
                float o1 = (c[mt][nt][hf * 2 + 1] - mean) * rstd * gv.y + bv.y;
                if (hasG2) {
                    __half2 h = __floats2half2_rn(o0, o1);
                    *(uint32_t*)(XS + row * XPH + col) = *(uint32_t*)&h;
                } else if (grow < M) {
                    float2 t = {o0, o1};
                    *(float2*)(OutF + grow * 256 + col) = t;
                }
            }
        }
    if (!hasG2) return;
    __syncthreads();

    #pragma unroll
    for (int i = 0; i < 2; ++i)
        #pragma unroll
        for (int j = 0; j < 8; ++j)
            #pragma unroll
            for (int k = 0; k < 4; ++k) c[i][j][k] = 0.f;

    gemm_h(W2, xs_b, ws_b, c, tid, wm, wn, lane);

    #pragma unroll
    for (int mt = 0; mt < 2; ++mt) {
        long rb = blockRow + wm * 32 + mt * 16;
        long r0 = rb + g;
        long r1 = rb + 8 + g;
        #pragma unroll
        for (int nt = 0; nt < 8; ++nt) {
            int col = wn * 64 + nt * 8 + tq * 2;
            if (r0 < M) {
                __half2 h = __floats2half2_rn(c[mt][nt][0], c[mt][nt][1]);
                *(uint32_t*)(OutH + r0 * 256 + col) = *(uint32_t*)&h;
            }
            if (r1 < M) {
                __half2 h = __floats2half2_rn(c[mt][nt][2], c[mt][nt][3]);
                *(uint32_t*)(OutH + r1 * 256 + col) = *(uint32_t*)&h;
            }
        }
    }
}

// --------------------------------- driver ---------------------------------

extern "C" void kernel_launch(void* const* d_in, const int* in_sizes, int n_in,
                              void* d_out, int out_size) {
    const int*   xcat = (const int*)d_in[0];
    const int*   ei   = (const int*)d_in[1];
    const float* e0   = (const float*)d_in[2];
    const float* e1   = (const float*)d_in[3];
    const float* e2   = (const float*)d_in[4];
    const float* e3   = (const float*)d_in[5];
    const float* w1a  = (const float*)d_in[6];
    const float* b1a  = (const float*)d_in[7];
    const float* w1b  = (const float*)d_in[8];
    const float* b1b  = (const float*)d_in[9];
    const float* w2a  = (const float*)d_in[10];
    const float* b2a  = (const float*)d_in[11];
    const float* w2b  = (const float*)d_in[12];
    const float* b2b  = (const float*)d_in[13];
    const float* ln1g = (const float*)d_in[14];
    const float* ln1b = (const float*)d_in[15];
    const float* ln2g = (const float*)d_in[16];
    const float* ln2b = (const float*)d_in[17];

    int M = in_sizes[0] / 4;
    int E = in_sizes[1] / 2;
    int V = in_sizes[2] / 64;

    __half *h0, *h1, *tabh, *hw1b, *hw2a, *hw2b;
    int *deg, *rowptr, *cursor, *csr;
    cudaGetSymbolAddress((void**)&h0, g_h0);
    cudaGetSymbolAddress((void**)&h1, g_h1);
    cudaGetSymbolAddress((void**)&tabh, g_tabh);
    cudaGetSymbolAddress((void**)&hw1b, g_w1b);
    cudaGetSymbolAddress((void**)&hw2a, g_w2a);
    cudaGetSymbolAddress((void**)&hw2b, g_w2b);
    cudaGetSymbolAddress((void**)&deg, g_deg);
    cudaGetSymbolAddress((void**)&rowptr, g_rowptr);
    cudaGetSymbolAddress((void**)&cursor, g_cursor);
    cudaGetSymbolAddress((void**)&csr, g_csr);

    cudaFuncSetAttribute(k_conv, cudaFuncAttributeMaxDynamicSharedMemorySize,
                         CONV_SMEM_BYTES);

    int rowGrid = (M + 7) / 8;
    int convGrid = (M + 63) / 64;

    int nCnt = (E / 4 + 255) / 256;           // count blocks
    int nVb = (V + 7) / 8;                    // table v-blocks per field
    int nCvt = (3 * DIM * DIM + 2047) / 2048; // weight-cvt blocks
    int nFill = nCnt;                          // fill blocks
    int nZ0 = (M * 32 + 255) / 256;           // z0 blocks

    // front1: CSR count || table build || weight cvt
    cudaMemsetAsync(deg, 0, (size_t)M * sizeof(int), 0);
    k_front1<<<nCnt + 4 * nVb + nCvt, 256>>>(ei, deg, E,
                                             e0, e1, e2, e3, w1a, tabh, V,
                                             w1b, hw1b, w2a, hw2a, w2b, hw2b,
                                             nCnt, nVb);
    k_scan<<<1, 1024>>>(deg, rowptr, cursor, M);
    // front2: CSR fill || z0
    k_front2<<<nFill + nZ0, 256>>>(ei, cursor, csr, E,
                                   xcat, tabh, h0, M, nFill);

    // conv1: a1 = agg(z0); h = LN1(relu(relu(a1+b1a)@W1b+b1b)); u = h@W2a
    k_agg<<<rowGrid, 256>>>(h0, h1, rowptr, csr, M);
    k_conv<<<convGrid, 256, CONV_SMEM_BYTES>>>(h1, b1a, hw1b, b1b, ln1g, ln1b,
                                               hw2a, h0, nullptr, M, 1, 1);

    // conv2: a2 = agg(u); out = LN2(relu(a2+b2a)@W2b+b2b)
    k_agg<<<rowGrid, 256>>>(h0, h1, rowptr, csr, M);
    k_conv<<<convGrid, 256, CONV_SMEM_BYTES>>>(h1, b2a, hw2b, b2b, ln2g, ln2b,
                                               nullptr, nullptr, (float*)d_out,
                                               M, 0, 0);
}